// round 1
// baseline (speedup 1.0000x reference)
#include <cuda_runtime.h>
#include <cstddef>

// Problem constants (from reference: B=64, NV=8192, NF=16384, N_DISCRETE=128)
#define NVERT 8192
#define NFACE 16384
#define NB    64
#define ROWL  (NFACE * 10 + 1)                 // 163841 tokens per batch row

static const size_t L1        = (size_t)NB * ROWL;          // input_ids elems (10,485,824)
static const size_t OFF_ATT   = L1;                          // attention_mask
static const size_t OFF_CODES = 2 * L1;                      // codes
static const size_t CSZ       = (size_t)NB * NFACE * 9;      // 9,437,184
static const size_t OFF_DISC  = OFF_CODES + CSZ;             // discrete_face_coords
static const size_t OFF_RECON = OFF_DISC + CSZ;              // recon_faces (576)

// Quantize the 9 coordinates of one face. Bit-exact vs the JAX reference:
// q = (t - LO)/(HI-LO)*128 - 0.5  ==  (t+1)*64 - 0.5  (÷2, ×128 exact pow2 ops)
// jnp.round == rintf (round-half-to-even), then clamp [0,127].
__device__ __forceinline__ void face_codes(const float* __restrict__ vb,
                                           const int*   __restrict__ fp,
                                           float* c) {
    int vi0 = __ldg(fp + 0);
    int vi1 = __ldg(fp + 1);
    int vi2 = __ldg(fp + 2);
    int vi[3] = {vi0, vi1, vi2};
#pragma unroll
    for (int v = 0; v < 3; v++) {
        const float* p = vb + (size_t)vi[v] * 3;
#pragma unroll
        for (int k = 0; k < 3; k++) {
            float t = __ldg(p + k);
            float q = (t + 1.0f) * 64.0f - 0.5f;
            float r = rintf(q);
            c[v * 3 + k] = fminf(fmaxf(r, 0.0f), 127.0f);
        }
    }
}

// One thread per face. Writes codes + discrete (identical) via float4, and
// recon_faces for face 0 of each batch (registers already hold its codes).
__global__ void k_codes(const float* __restrict__ verts,
                        const int*   __restrict__ faces,
                        float*       __restrict__ out) {
    __shared__ float s[256 * 9];
    const int t  = threadIdx.x;
    const int gf = blockIdx.x * 256 + t;          // global face id
    const int b  = gf >> 14;                      // NF = 2^14

    float c[9];
    face_codes(verts + (size_t)b * NVERT * 3, faces + (size_t)gf * 3, c);

#pragma unroll
    for (int k = 0; k < 9; k++) s[t * 9 + k] = c[k];   // stride 9: conflict-free
    __syncthreads();

    const size_t base = (size_t)blockIdx.x * 2304;     // 256 faces * 9, /4 ok
    const float4* src = (const float4*)s;
    float4* d1 = (float4*)(out + OFF_CODES + base);
    float4* d2 = (float4*)(out + OFF_DISC  + base);
    for (int i = t; i < 576; i += 256) {               // 2304/4 float4s
        float4 v = src[i];
        d1[i] = v;
        d2[i] = v;
    }

    if ((gf & (NFACE - 1)) == 0) {                     // face 0 of batch b
        float* r = out + OFF_RECON + (size_t)b * 9;
#pragma unroll
        for (int k = 0; k < 9; k++)
            r[k] = (c[k] + 0.5f) * (1.0f / 64.0f) - 1.0f;  // exact-equiv undiscretize
    }
}

// One thread per face: stage [9 tokens + SEP] per face into smem, then
// coalesced scalar stores (warp = 128B contiguous per instruction).
// Sequence layout per batch row: [-1][f0 tok0..8][SEP]...[f16383 tok0..8][-1]
__global__ void k_ids(const float* __restrict__ verts,
                      const int*   __restrict__ faces,
                      float*       __restrict__ out) {
    __shared__ float s[2560];
    const int t  = threadIdx.x;
    const int gf = blockIdx.x * 256 + t;
    const int b  = gf >> 14;

    float c[9];
    face_codes(verts + (size_t)b * NVERT * 3, faces + (size_t)gf * 3, c);

#pragma unroll
    for (int k = 0; k < 9; k++) s[t * 10 + k] = c[k];
    // trailing separator; last face of the batch gets the final PAD (-1)
    s[t * 10 + 9] = ((gf & (NFACE - 1)) == (NFACE - 1)) ? -1.0f : 128.0f;
    __syncthreads();

    const int lf0 = (blockIdx.x * 256) & (NFACE - 1);   // blocks never straddle batches
    float* dst = out + (size_t)b * ROWL + 1 + (size_t)lf0 * 10;
#pragma unroll
    for (int i = 0; i < 10; i++)
        dst[t + i * 256] = s[t + i * 256];

    if (t == 0 && lf0 == 0)
        out[(size_t)b * ROWL] = -1.0f;                  // leading PAD
}

// attention_mask = 1.0 everywhere (L1 elems, /4 aligned).
__global__ void k_fill(float* __restrict__ out) {
    const size_t n = L1 / 4;
    float4* d = (float4*)(out + OFF_ATT);
    const float4 one = make_float4(1.0f, 1.0f, 1.0f, 1.0f);
    for (size_t i = (size_t)blockIdx.x * blockDim.x + threadIdx.x; i < n;
         i += (size_t)gridDim.x * blockDim.x)
        d[i] = one;
}

extern "C" void kernel_launch(void* const* d_in, const int* in_sizes, int n_in,
                              void* d_out, int out_size) {
    const float* verts = (const float*)d_in[0];
    const int*   faces = (const int*)d_in[1];
    float*       out   = (float*)d_out;

    const int nblk = (NB * NFACE) / 256;   // 4096
    k_codes<<<nblk, 256>>>(verts, faces, out);
    k_ids  <<<nblk, 256>>>(verts, faces, out);
    k_fill <<<4736, 256>>>(out);
}

// round 2
// speedup vs baseline: 1.1573x; 1.1573x over previous
#include <cuda_runtime.h>
#include <cstddef>

// Problem constants (reference: B=64, NV=8192, NF=16384, N_DISCRETE=128)
#define NVERT   8192
#define NFACE   16384
#define NB      64
#define ROWL    (NFACE * 10 + 1)          // 163841 tokens per batch row
#define THREADS 512
#define FPB     8192                      // faces per block (2 blocks / batch)
#define ITERS   (FPB / THREADS)           // 16

static const size_t L1        = (size_t)NB * ROWL;          // input_ids elems
static const size_t OFF_ATT   = L1;                          // attention_mask
static const size_t OFF_CODES = 2 * L1;                      // codes
static const size_t CSZ       = (size_t)NB * NFACE * 9;
static const size_t OFF_DISC  = OFF_CODES + CSZ;             // discrete_face_coords
static const size_t OFF_RECON = OFF_DISC + CSZ;              // recon_faces

// smem layout (floats): vertex cache (float4-padded) | ids staging | codes staging
#define S_VTX_F   (NVERT * 4)             // 32768 floats = 128 KB
#define S_IDS_F   (THREADS * 10)          // 5120 floats
#define S_COD_F   (THREADS * 9)           // 4608 floats
#define SMEM_BYTES ((S_VTX_F + S_IDS_F + S_COD_F) * 4)   // 169,984 B

__device__ __forceinline__ float quant(float t) {
    // bit-exact vs reference: (t-LO)/(HI-LO)*128 - 0.5 == (t+1)*64 - 0.5
    float r = rintf((t + 1.0f) * 64.0f - 0.5f);   // jnp.round == rint (half-even)
    return fminf(fmaxf(r, 0.0f), 127.0f);
}

__global__ void __launch_bounds__(THREADS, 1)
k_fused(const float* __restrict__ verts,
        const int*   __restrict__ faces,
        float*       __restrict__ out) {
    extern __shared__ float smem[];
    float* s_vtx = smem;
    float* s_ids = smem + S_VTX_F;
    float* s_cod = smem + S_VTX_F + S_IDS_F;

    const int t     = threadIdx.x;
    const int b     = blockIdx.x >> 1;            // batch
    const int half  = blockIdx.x & 1;
    const int f0blk = b * NFACE + half * FPB;     // first global face of block

    // ---- stage this batch's vertices into smem, padded to float4 ----
    const float* vb = verts + (size_t)b * NVERT * 3;
    for (int i = t; i < NVERT * 3; i += THREADS) {
        int v = i / 3;
        int k = i - v * 3;
        s_vtx[v * 4 + k] = vb[i];                 // coalesced read, one-time
    }

    // ---- attention_mask = 1.0 (grid-stride float4 fill, no smem needed) ----
    {
        float4* d = (float4*)(out + OFF_ATT);
        const float4 one = make_float4(1.0f, 1.0f, 1.0f, 1.0f);
        const size_t n4 = L1 / 4;
        for (size_t i = (size_t)blockIdx.x * THREADS + t; i < n4;
             i += (size_t)gridDim.x * THREADS)
            d[i] = one;
    }
    if (half == 0 && t == 0)
        out[(size_t)b * ROWL] = -1.0f;            // leading PAD of this row

    __syncthreads();                              // vertex cache ready

    for (int it = 0; it < ITERS; ++it) {
        const int f = f0blk + it * THREADS + t;   // global face id

        // gather 3 vertices from smem (LDS.128 each) + quantize
        const int* fp = faces + (size_t)f * 3;
        int v0 = __ldg(fp + 0);
        int v1 = __ldg(fp + 1);
        int v2 = __ldg(fp + 2);
        float4 p0 = *(const float4*)&s_vtx[v0 * 4];
        float4 p1 = *(const float4*)&s_vtx[v1 * 4];
        float4 p2 = *(const float4*)&s_vtx[v2 * 4];

        float c[9];
        c[0] = quant(p0.x); c[1] = quant(p0.y); c[2] = quant(p0.z);
        c[3] = quant(p1.x); c[4] = quant(p1.y); c[5] = quant(p1.z);
        c[6] = quant(p2.x); c[7] = quant(p2.y); c[8] = quant(p2.z);

        if (it) __syncthreads();                  // staging buffers free again

#pragma unroll
        for (int k = 0; k < 9; k++) {
            s_ids[t * 10 + k] = c[k];             // 2-way conflict (stride 10)
            s_cod[t * 9 + k]  = c[k];             // conflict-free (stride 9)
        }
        // trailing separator; the very last face of the row gets the final PAD
        s_ids[t * 10 + 9] = ((f & (NFACE - 1)) == (NFACE - 1)) ? -1.0f : 128.0f;
        __syncthreads();

        // ---- input_ids: 10 perfectly coalesced STG.32 per thread ----
        const int lf0 = half * FPB + it * THREADS;    // batch-local face of elem 0
        float* dst = out + (size_t)b * ROWL + 1 + (size_t)lf0 * 10;
#pragma unroll
        for (int i = 0; i < 10; i++)
            dst[t + i * THREADS] = s_ids[t + i * THREADS];

        // ---- codes + discrete (identical): float4 stores ----
        const size_t cb = (size_t)(f0blk + it * THREADS) * 9;   // mult of 4608
        const float4* src = (const float4*)s_cod;
        float4* d1 = (float4*)(out + OFF_CODES + cb);
        float4* d2 = (float4*)(out + OFF_DISC  + cb);
        for (int i = t; i < (THREADS * 9) / 4; i += THREADS) {  // 1152 float4
            float4 v = src[i];
            d1[i] = v;
            d2[i] = v;
        }

        // ---- recon_faces from face 0 of each batch (registers in hand) ----
        if ((f & (NFACE - 1)) == 0) {
            float* r = out + OFF_RECON + (size_t)b * 9;
#pragma unroll
            for (int k = 0; k < 9; k++)
                r[k] = (c[k] + 0.5f) * (1.0f / 64.0f) - 1.0f;
        }
    }
}

extern "C" void kernel_launch(void* const* d_in, const int* in_sizes, int n_in,
                              void* d_out, int out_size) {
    const float* verts = (const float*)d_in[0];
    const int*   faces = (const int*)d_in[1];
    float*       out   = (float*)d_out;

    cudaFuncSetAttribute(k_fused, cudaFuncAttributeMaxDynamicSharedMemorySize,
                         SMEM_BYTES);
    k_fused<<<NB * 2, THREADS, SMEM_BYTES>>>(verts, faces, out);
}

// round 3
// speedup vs baseline: 1.2943x; 1.1184x over previous
#include <cuda_runtime.h>
#include <cstddef>

// Problem constants (reference: B=64, NV=8192, NF=16384, N_DISCRETE=128)
#define NVERT   8192
#define NFACE   16384
#define NB      64
#define ROWL    (NFACE * 10 + 1)          // 163841 tokens per batch row
#define THREADS 256

static const size_t L1        = (size_t)NB * ROWL;          // input_ids elems
static const size_t OFF_ATT   = L1;                          // attention_mask
static const size_t OFF_CODES = 2 * L1;                      // codes
static const size_t CSZ       = (size_t)NB * NFACE * 9;
static const size_t OFF_DISC  = OFF_CODES + CSZ;             // discrete_face_coords
static const size_t OFF_RECON = OFF_DISC + CSZ;              // recon_faces

// float4-padded vertex table (8 MB static scratch; L2-resident at use time)
__device__ float4 g_vpad[NB * NVERT];

__device__ __forceinline__ float quant(float t) {
    // bit-exact vs reference: (t-LO)/(HI-LO)*128 - 0.5 == (t+1)*64 - 0.5
    float r = rintf((t + 1.0f) * 64.0f - 0.5f);   // jnp.round == rint (half-even)
    return fminf(fmaxf(r, 0.0f), 127.0f);
}

// ---- pre-pass: pad (x,y,z) -> float4 slots ----
__global__ void k_pad(const float* __restrict__ verts) {
    float* dst = (float*)g_vpad;
    const int n = NB * NVERT * 3;
    for (int i = blockIdx.x * blockDim.x + threadIdx.x; i < n;
         i += gridDim.x * blockDim.x) {
        int v = i / 3;
        int k = i - v * 3;
        dst[v * 4 + k] = verts[i];
    }
}

// ---- fused tokenizer: 256 faces per CTA, 4096 CTAs ----
__global__ void __launch_bounds__(THREADS)
k_fused(const int* __restrict__ faces, float* __restrict__ out) {
    __shared__ float s_ids[THREADS * 10];
    __shared__ float s_cod[THREADS * 9];

    const int t  = threadIdx.x;
    const int gf = blockIdx.x * THREADS + t;   // global face id
    const int b  = gf >> 14;                   // NF = 2^14

    // gather 3 vertices (scattered LDG.128, L2-resident) + quantize
    const int* fp = faces + (size_t)gf * 3;
    int v0 = __ldg(fp + 0);
    int v1 = __ldg(fp + 1);
    int v2 = __ldg(fp + 2);
    const float4* vb = g_vpad + (size_t)b * NVERT;
    float4 p0 = __ldg(vb + v0);
    float4 p1 = __ldg(vb + v1);
    float4 p2 = __ldg(vb + v2);

    float c[9];
    c[0] = quant(p0.x); c[1] = quant(p0.y); c[2] = quant(p0.z);
    c[3] = quant(p1.x); c[4] = quant(p1.y); c[5] = quant(p1.z);
    c[6] = quant(p2.x); c[7] = quant(p2.y); c[8] = quant(p2.z);

#pragma unroll
    for (int k = 0; k < 9; k++) {
        s_ids[t * 10 + k] = c[k];              // 2-way bank conflict (stride 10)
        s_cod[t * 9 + k]  = c[k];              // conflict-free (stride 9)
    }
    // trailing separator; very last face of the row gets the final PAD (-1)
    s_ids[t * 10 + 9] = ((gf & (NFACE - 1)) == (NFACE - 1)) ? -1.0f : 128.0f;

    // ---- attention_mask = 1.0: grid-stride float4 fill (overlaps sync) ----
    {
        float4* d = (float4*)(out + OFF_ATT);
        const float4 one = make_float4(1.0f, 1.0f, 1.0f, 1.0f);
        const size_t n4 = L1 / 4;
        for (size_t i = (size_t)blockIdx.x * THREADS + t; i < n4;
             i += (size_t)gridDim.x * THREADS)
            d[i] = one;
    }
    __syncthreads();

    // ---- input_ids: 10 perfectly coalesced STG.32 per thread ----
    const int lf0 = (blockIdx.x * THREADS) & (NFACE - 1);  // blocks don't straddle batches
    float* dst = out + (size_t)b * ROWL + 1 + (size_t)lf0 * 10;
#pragma unroll
    for (int i = 0; i < 10; i++)
        dst[t + i * THREADS] = s_ids[t + i * THREADS];

    // ---- codes + discrete (identical copies): float4 stores ----
    const size_t cb = (size_t)blockIdx.x * (THREADS * 9);  // multiple of 4 floats
    const float4* src = (const float4*)s_cod;
    float4* d1 = (float4*)(out + OFF_CODES + cb);
    float4* d2 = (float4*)(out + OFF_DISC  + cb);
#pragma unroll
    for (int i = 0; i < (THREADS * 9) / 4 / THREADS + 1; i++) {  // 576/256 -> 3 iters, guarded
        int idx = t + i * THREADS;
        if (idx < (THREADS * 9) / 4) {
            float4 v = src[idx];
            d1[idx] = v;
            d2[idx] = v;
        }
    }

    // ---- per-batch extras from registers ----
    if ((gf & (NFACE - 1)) == 0) {             // face 0 of batch b
        out[(size_t)b * ROWL] = -1.0f;         // leading PAD
        float* r = out + OFF_RECON + (size_t)b * 9;
#pragma unroll
        for (int k = 0; k < 9; k++)
            r[k] = (c[k] + 0.5f) * (1.0f / 64.0f) - 1.0f;
    }
}

extern "C" void kernel_launch(void* const* d_in, const int* in_sizes, int n_in,
                              void* d_out, int out_size) {
    const float* verts = (const float*)d_in[0];
    const int*   faces = (const int*)d_in[1];
    float*       out   = (float*)d_out;

    k_pad  <<<1184, 256>>>(verts);                       // 8 blocks/SM worth
    k_fused<<<(NB * NFACE) / THREADS, THREADS>>>(faces, out);
}

// round 4
// speedup vs baseline: 1.5848x; 1.2244x over previous
#include <cuda_runtime.h>
#include <cstddef>

// Problem constants (reference: B=64, NV=8192, NF=16384, N_DISCRETE=128)
#define NVERT   8192
#define NFACE   16384
#define NB      64
#define ROWL    (NFACE * 10 + 1)            // 163841 tokens per batch row
#define THREADS 256
#define FPC     1024                        // faces per CTA
#define ITERS   (FPC / THREADS)             // 4

static const size_t L1        = (size_t)NB * ROWL;          // input_ids elems
static const size_t OFF_ATT   = L1;                          // attention_mask
static const size_t OFF_CODES = 2 * L1;                      // codes
static const size_t CSZ       = (size_t)NB * NFACE * 9;
static const size_t OFF_DISC  = OFF_CODES + CSZ;             // discrete_face_coords
static const size_t OFF_RECON = OFF_DISC + CSZ;              // recon_faces

// packed per-vertex codes: c0 | c1<<8 | c2<<16  (2 MB static scratch)
__device__ unsigned int g_vcode[NB * NVERT];

__device__ __forceinline__ int quant(float t) {
    // bit-exact vs reference: (t-LO)/(HI-LO)*128 - 0.5 == (t+1)*64 - 0.5
    float r = rintf((t + 1.0f) * 64.0f - 0.5f);   // jnp.round == rint (half-even)
    return (int)fminf(fmaxf(r, 0.0f), 127.0f);    // exact small int
}

// ---- pre-pass: quantize+pack vertices, fill attention_mask, leading PADs ----
__global__ void k_pre(const float* __restrict__ verts, float* __restrict__ out) {
    const int v = blockIdx.x * blockDim.x + threadIdx.x;   // global vertex id
    if (v < NB * NVERT) {
        const float* p = verts + (size_t)v * 3;
        unsigned int pk = (unsigned int)quant(__ldg(p + 0))
                        | ((unsigned int)quant(__ldg(p + 1)) << 8)
                        | ((unsigned int)quant(__ldg(p + 2)) << 16);
        g_vcode[v] = pk;
    }
    // attention_mask = 1.0 (grid-stride float4 fill)
    {
        float4* d = (float4*)(out + OFF_ATT);
        const float4 one = make_float4(1.0f, 1.0f, 1.0f, 1.0f);
        const size_t n4 = L1 / 4;
        for (size_t i = (size_t)blockIdx.x * blockDim.x + threadIdx.x; i < n4;
             i += (size_t)gridDim.x * blockDim.x)
            d[i] = one;
    }
    // leading PAD of each batch row
    if (threadIdx.x == 0 && blockIdx.x < NB)
        out[(size_t)blockIdx.x * ROWL] = -1.0f;
}

// ---- fused tokenizer: packed vertex-code table in smem, LDS gather ----
__global__ void __launch_bounds__(THREADS)
k_fused(const int* __restrict__ faces, float* __restrict__ out) {
    __shared__ unsigned int s_tab[NVERT];          // 32 KB packed codes
    __shared__ float        s_ids[THREADS * 10];   // 10 KB
    __shared__ float        s_cod[THREADS * 9];    //  9 KB

    const int t   = threadIdx.x;
    const int gf0 = blockIdx.x * FPC;              // first face of CTA
    const int b   = gf0 >> 14;                     // batch (FPC divides NFACE)

    // stage this batch's packed table: 2048 uint4, coalesced
    {
        const uint4* src = (const uint4*)(g_vcode + (size_t)b * NVERT);
        uint4* dst = (uint4*)s_tab;
#pragma unroll
        for (int i = 0; i < (NVERT / 4) / THREADS; i++)   // 8 per thread
            dst[t + i * THREADS] = __ldg(src + t + i * THREADS);
    }
    __syncthreads();

    for (int it = 0; it < ITERS; ++it) {
        const int f = gf0 + it * THREADS + t;      // global face id

        const int* fp = faces + (size_t)f * 3;
        unsigned int pk0 = s_tab[__ldg(fp + 0)];   // 3 scattered LDS.32
        unsigned int pk1 = s_tab[__ldg(fp + 1)];
        unsigned int pk2 = s_tab[__ldg(fp + 2)];

        float c[9];
        c[0] = (float)( pk0        & 0xFF);
        c[1] = (float)((pk0 >>  8) & 0xFF);
        c[2] = (float)((pk0 >> 16) & 0xFF);
        c[3] = (float)( pk1        & 0xFF);
        c[4] = (float)((pk1 >>  8) & 0xFF);
        c[5] = (float)((pk1 >> 16) & 0xFF);
        c[6] = (float)( pk2        & 0xFF);
        c[7] = (float)((pk2 >>  8) & 0xFF);
        c[8] = (float)((pk2 >> 16) & 0xFF);

        if (it) __syncthreads();                   // staging buffers reusable
#pragma unroll
        for (int k = 0; k < 9; k++) {
            s_ids[t * 10 + k] = c[k];              // 2-way conflict (stride 10)
            s_cod[t * 9 + k]  = c[k];              // conflict-free (stride 9)
        }
        // trailing separator; very last face of the row gets the final PAD (-1)
        s_ids[t * 10 + 9] = ((f & (NFACE - 1)) == (NFACE - 1)) ? -1.0f : 128.0f;
        __syncthreads();

        // ---- input_ids: 10 perfectly coalesced STG.32 per thread ----
        const int lf0 = (gf0 & (NFACE - 1)) + it * THREADS;   // batch-local face 0
        float* dst = out + (size_t)b * ROWL + 1 + (size_t)lf0 * 10;
#pragma unroll
        for (int i = 0; i < 10; i++)
            dst[t + i * THREADS] = s_ids[t + i * THREADS];

        // ---- codes + discrete (identical copies): float4 stores ----
        const size_t cb = (size_t)(gf0 + it * THREADS) * 9;   // multiple of 2304
        const float4* src = (const float4*)s_cod;
        float4* d1 = (float4*)(out + OFF_CODES + cb);
        float4* d2 = (float4*)(out + OFF_DISC  + cb);
#pragma unroll
        for (int i = 0; i < 3; i++) {              // 576 float4s, 256 threads
            int idx = t + i * THREADS;
            if (idx < (THREADS * 9) / 4) {
                float4 v = src[idx];
                d1[idx] = v;
                d2[idx] = v;
            }
        }

        // ---- recon_faces from face 0 of each batch (registers in hand) ----
        if ((f & (NFACE - 1)) == 0) {
            float* r = out + OFF_RECON + (size_t)b * 9;
#pragma unroll
            for (int k = 0; k < 9; k++)
                r[k] = (c[k] + 0.5f) * (1.0f / 64.0f) - 1.0f;
        }
    }
}

extern "C" void kernel_launch(void* const* d_in, const int* in_sizes, int n_in,
                              void* d_out, int out_size) {
    const float* verts = (const float*)d_in[0];
    const int*   faces = (const int*)d_in[1];
    float*       out   = (float*)d_out;

    k_pre  <<<(NB * NVERT) / 256, 256>>>(verts, out);        // 2048 blocks
    k_fused<<<(NB * NFACE) / FPC, THREADS>>>(faces, out);    // 1024 blocks
}

// round 5
// speedup vs baseline: 1.8324x; 1.1562x over previous
#include <cuda_runtime.h>
#include <cstddef>

// Problem constants (reference: B=64, NV=8192, NF=16384, N_DISCRETE=128)
#define NVERT   8192
#define NFACE   16384
#define NB      64
#define ROWL    (NFACE * 10 + 1)            // 163841 tokens per batch row
#define THREADS 256
#define FPC     1024                        // faces per CTA
#define ITERS   (FPC / THREADS)             // 4

static const size_t L1        = (size_t)NB * ROWL;          // input_ids elems
static const size_t OFF_ATT   = L1;                          // attention_mask
static const size_t OFF_CODES = 2 * L1;                      // codes
static const size_t CSZ       = (size_t)NB * NFACE * 9;
static const size_t OFF_DISC  = OFF_CODES + CSZ;             // discrete_face_coords
static const size_t OFF_RECON = OFF_DISC + CSZ;              // recon_faces

// packed per-vertex codes: c0 | c1<<8 | c2<<16  (2 MB static scratch)
__device__ unsigned int g_vcode[NB * NVERT];

__device__ __forceinline__ int quant(float t) {
    // bit-exact vs reference: (t-LO)/(HI-LO)*128 - 0.5 == (t+1)*64 - 0.5
    float r = rintf((t + 1.0f) * 64.0f - 0.5f);   // jnp.round == rint (half-even)
    return (int)fminf(fmaxf(r, 0.0f), 127.0f);    // exact small int
}

// ---- pre-pass: quantize+pack vertices only (14 MB traffic) ----
__global__ void k_pre(const float* __restrict__ verts) {
    const int v = blockIdx.x * blockDim.x + threadIdx.x;   // global vertex id
    const float* p = verts + (size_t)v * 3;
    g_vcode[v] = (unsigned int)quant(__ldg(p + 0))
               | ((unsigned int)quant(__ldg(p + 1)) << 8)
               | ((unsigned int)quant(__ldg(p + 2)) << 16);
}

// ---- fused tokenizer: smem code table + single stride-10 staging buffer ----
__global__ void __launch_bounds__(THREADS, 5)
k_fused(const int* __restrict__ faces, float* __restrict__ out) {
    __shared__ unsigned int s_tab[NVERT];          // 32 KB packed codes
    __shared__ float        s_stage[THREADS * 10]; // 10 KB

    const int t   = threadIdx.x;
    const int gf0 = blockIdx.x * FPC;              // first face of CTA
    const int b   = gf0 >> 14;                     // batch (FPC divides NFACE)

    // stage this batch's packed table: 2048 uint4, coalesced
    {
        const uint4* src = (const uint4*)(g_vcode + (size_t)b * NVERT);
        uint4* dst = (uint4*)s_tab;
#pragma unroll
        for (int i = 0; i < (NVERT / 4) / THREADS; i++)   // 8 per thread
            dst[t + i * THREADS] = __ldg(src + t + i * THREADS);
    }
    __syncthreads();

    for (int it = 0; it < ITERS; ++it) {
        const int f = gf0 + it * THREADS + t;      // global face id

        const int* fp = faces + (size_t)f * 3;
        int vi0 = __ldg(fp + 0);
        int vi1 = __ldg(fp + 1);
        int vi2 = __ldg(fp + 2);
        unsigned int pk0 = s_tab[vi0];             // 3 scattered LDS.32
        unsigned int pk1 = s_tab[vi1];
        unsigned int pk2 = s_tab[vi2];

        float c[9];
        c[0] = (float)( pk0        & 0xFF);
        c[1] = (float)((pk0 >>  8) & 0xFF);
        c[2] = (float)((pk0 >> 16) & 0xFF);
        c[3] = (float)( pk1        & 0xFF);
        c[4] = (float)((pk1 >>  8) & 0xFF);
        c[5] = (float)((pk1 >> 16) & 0xFF);
        c[6] = (float)( pk2        & 0xFF);
        c[7] = (float)((pk2 >> 16) & 0xFF);        // placeholder fixed below
        c[7] = (float)((pk2 >>  8) & 0xFF);
        c[8] = (float)((pk2 >> 16) & 0xFF);

        if (it) __syncthreads();                   // staging buffer reusable
#pragma unroll
        for (int k = 0; k < 9; k++)
            s_stage[t * 10 + k] = c[k];            // 2-way conflict (stride 10)
        // trailing separator; very last face of the row gets the final PAD (-1)
        s_stage[t * 10 + 9] = ((f & (NFACE - 1)) == (NFACE - 1)) ? -1.0f : 128.0f;
        __syncthreads();

        // ---- input_ids: 10 perfectly coalesced STG.32 per thread ----
        const int lf0 = (gf0 & (NFACE - 1)) + it * THREADS;   // batch-local face 0
        float* dst = out + (size_t)b * ROWL + 1 + (size_t)lf0 * 10;
#pragma unroll
        for (int i = 0; i < 10; i++)
            __stcs(dst + t + i * THREADS, s_stage[t + i * THREADS]);

        // ---- codes + discrete: gather stride-10 -> pack float4 -> STG.128 ----
        const size_t cb = (size_t)(gf0 + it * THREADS) * 9;   // multiple of 2304
        float4* d1 = (float4*)(out + OFF_CODES + cb);
        float4* d2 = (float4*)(out + OFF_DISC  + cb);
#pragma unroll
        for (int i = 0; i < 3; i++) {              // 576 float4s over 256 threads
            int idx4 = t + i * THREADS;
            if (idx4 < (THREADS * 9) / 4) {
                int j = idx4 * 4;
                float4 v;
                int q0 = j / 9,       r0 = j - q0 * 9;
                int q1 = (j + 1) / 9, r1 = (j + 1) - q1 * 9;
                int q2 = (j + 2) / 9, r2 = (j + 2) - q2 * 9;
                int q3 = (j + 3) / 9, r3 = (j + 3) - q3 * 9;
                v.x = s_stage[q0 * 10 + r0];
                v.y = s_stage[q1 * 10 + r1];
                v.z = s_stage[q2 * 10 + r2];
                v.w = s_stage[q3 * 10 + r3];
                __stcs(d1 + idx4, v);
                __stcs(d2 + idx4, v);
            }
        }

        // ---- per-batch extras from registers ----
        if ((f & (NFACE - 1)) == 0) {              // face 0 of batch b
            out[(size_t)b * ROWL] = -1.0f;         // leading PAD
            float* r = out + OFF_RECON + (size_t)b * 9;
#pragma unroll
            for (int k = 0; k < 9; k++)
                r[k] = (c[k] + 0.5f) * (1.0f / 64.0f) - 1.0f;
        }
    }

    // ---- attention_mask = 1.0: grid-stride float4 streaming fill ----
    {
        float4* d = (float4*)(out + OFF_ATT);
        const float4 one = make_float4(1.0f, 1.0f, 1.0f, 1.0f);
        const size_t n4 = L1 / 4;
        for (size_t i = (size_t)blockIdx.x * THREADS + t; i < n4;
             i += (size_t)gridDim.x * THREADS)
            __stcs(d + i, one);
    }
}

extern "C" void kernel_launch(void* const* d_in, const int* in_sizes, int n_in,
                              void* d_out, int out_size) {
    const float* verts = (const float*)d_in[0];
    const int*   faces = (const int*)d_in[1];
    float*       out   = (float*)d_out;

    k_pre  <<<(NB * NVERT) / 256, 256>>>(verts);             // 2048 blocks
    k_fused<<<(NB * NFACE) / FPC, THREADS>>>(faces, out);    // 1024 blocks
}